// round 12
// baseline (speedup 1.0000x reference)
#include <cuda_runtime.h>
#include <cuda_fp16.h>

// LogicDense: out[i][j] = c0 + c1*a + c2*b + c3*a*b
//   a = x[i, idx0[j]], b = x[i, idx1[j]]
//
// R12 vs R11 (38.7 us main; all pipes ~50% = stage/compute PHASE SERIALIZATION):
//  - Persistent warp-specialized kernel: 256 producer threads stage tile t+1
//    (LDG -> fp16 -> swizzled STS) while 512 consumer threads compute tile t
//    (LDS gathers + FMA + STG.64). Double-buffered 2 x 64 KiB smem tiles,
//    named-barrier full/empty handoff (bar.arrive / bar.sync, count 768).
//  - grid = #SMs (persistent), groups walked grid-stride.
//  - precompute: warp-ballot dtype detect (no smem reduction), float4 w loads
//    -> cuts the fixed ~8.9 us total-main gap.

#define ROWS   8
#define NCONS  512
#define NPROD  256
#define THREADS (NCONS + NPROD)
#define MAX_OUT 16384

// named barrier ids: full[p] = 1+p, empty[p] = 3+p  (p = buffer parity)
#define BAR_SYNC(id)   asm volatile("bar.sync %0, %1;"   :: "r"(id), "r"(THREADS) : "memory")
#define BAR_ARRIVE(id) asm volatile("bar.arrive %0, %1;" :: "r"(id), "r"(THREADS) : "memory")

__device__ uint4 g_tabE[MAX_OUT / 2];  // records for even columns 2p
__device__ uint4 g_tabO[MAX_OUT / 2];  // records for odd  columns 2p+1
// record: .x=h2(c0,c1) .y=h2(c2,c3) .z=offA|offB<<16 .w=pad

__constant__ float c_T[64] = {
    0.f, 0.f, 0.f, 0.f,
    0.f, 0.f, 0.f, 1.f,
    0.f, 1.f, 0.f,-1.f,
    0.f, 1.f, 0.f, 0.f,
    0.f, 0.f, 1.f,-1.f,
    0.f, 0.f, 1.f, 0.f,
    0.f, 1.f, 1.f,-2.f,
    0.f, 1.f, 1.f,-1.f,
    1.f,-1.f,-1.f, 1.f,
    1.f,-1.f,-1.f, 2.f,
    1.f, 0.f,-1.f, 0.f,
    1.f, 0.f,-1.f, 1.f,
    1.f,-1.f, 0.f, 0.f,
    1.f,-1.f, 0.f, 1.f,
    1.f, 0.f, 0.f,-1.f,
    1.f, 0.f, 0.f, 0.f
};

__device__ __forceinline__ int swz_off(int idx) {
    // half-index of the 8-row group of element idx in the swizzled tile
    return (idx << 3) ^ (((idx >> 3) & 7) << 3);
}

__global__ void precompute_kernel(const void* __restrict__ idx_raw,
                                  const float* __restrict__ w,
                                  int out_dim) {
    // dtype detect: odd u32 words of the first 64 words are all zero iff the
    // buffer is int64 (high words of indices < in_dim). Warp-ballot, no smem.
    const unsigned int* u = (const unsigned int*)idx_raw;
    unsigned int probe = u[2 * (threadIdx.x & 31) + 1];
    const int is64 = !__any_sync(0xFFFFFFFFu, probe != 0u);

    int j = blockIdx.x * blockDim.x + threadIdx.x;
    if (j >= out_dim) return;

    const float4* w4 = (const float4*)(w + (size_t)j * 16);
    float4 wa = w4[0], wb = w4[1], wc = w4[2], wd = w4[3];
    float wv[16] = {wa.x, wa.y, wa.z, wa.w, wb.x, wb.y, wb.z, wb.w,
                    wc.x, wc.y, wc.z, wc.w, wd.x, wd.y, wd.z, wd.w};
    float m = -1e30f;
#pragma unroll
    for (int k = 0; k < 16; k++) m = fmaxf(m, wv[k]);
    float s = 0.f;
#pragma unroll
    for (int k = 0; k < 16; k++) {
        wv[k] = __expf(wv[k] - m);
        s += wv[k];
    }
    float inv = 1.f / s;
    float c0 = 0.f, c1 = 0.f, c2 = 0.f, c3 = 0.f;
#pragma unroll
    for (int k = 0; k < 16; k++) {
        float p = wv[k] * inv;
        c0 = fmaf(p, c_T[4 * k + 0], c0);
        c1 = fmaf(p, c_T[4 * k + 1], c1);
        c2 = fmaf(p, c_T[4 * k + 2], c2);
        c3 = fmaf(p, c_T[4 * k + 3], c3);
    }

    int i0, i1;
    if (is64) {
        const long long* p = (const long long*)idx_raw;
        i0 = (int)p[j];
        i1 = (int)p[out_dim + j];
    } else {
        const int* p = (const int*)idx_raw;
        i0 = p[j];
        i1 = p[out_dim + j];
    }

    __half2 c01 = __floats2half2_rn(c0, c1);
    __half2 c23 = __floats2half2_rn(c2, c3);
    uint4 rec;
    rec.x = *(unsigned int*)&c01;
    rec.y = *(unsigned int*)&c23;
    rec.z = (unsigned int)swz_off(i0) | ((unsigned int)swz_off(i1) << 16);
    rec.w = 0u;
    if (j & 1) g_tabO[j >> 1] = rec;
    else       g_tabE[j >> 1] = rec;
}

__device__ __forceinline__ unsigned int pack_h2(float lo, float hi) {
    __half2 h = __floats2half2_rn(lo, hi);
    return *(unsigned int*)&h;
}

__device__ __forceinline__ float2 h22f2(unsigned int u) {
    return __half22float2(*(const __half2*)&u);
}

template <bool FULL>
__global__ __launch_bounds__(THREADS) void logic_persist_kernel(
    const float* __restrict__ x,
    float* __restrict__ out,
    int in_dim, int out_dim, int batch, int ngroups) {
    extern __shared__ __half sh[];   // 2 buffers of in_dim*8 halfs, swizzled

    const int tid = threadIdx.x;
    const int tile_halfs = in_dim * ROWS;
    // number of groups this block handles (grid-stride g = bid + t*gridDim.x)
    const int G = (ngroups - (int)blockIdx.x + (int)gridDim.x - 1) / (int)gridDim.x;

    if (tid >= NCONS) {
        // ---------------- producer: 256 threads ----------------
        const int ptid = tid - NCONS;
        const int n4 = in_dim >> 2;
        for (int t = 0; t < G; t++) {
            const int g  = (int)blockIdx.x + t * (int)gridDim.x;
            const int rb = g * ROWS;
            __half* shp = sh + (t & 1) * tile_halfs;
            if (t >= 2) BAR_SYNC(3 + (t & 1));     // wait buffer consumed

            const float* xb = x + (size_t)rb * in_dim;
            for (int i = ptid; i < n4; i += NPROD) {
                float4 r[ROWS];
#pragma unroll
                for (int rr = 0; rr < ROWS; rr++) {
                    const int row = (FULL || rb + rr < batch) ? rr : 0;
                    r[rr] = *(const float4*)(xb + (size_t)row * in_dim + (i << 2));
                }
#pragma unroll
                for (int k = 0; k < 4; k++) {
                    uint4 pk;
                    pk.x = pack_h2((&r[0].x)[k], (&r[1].x)[k]);
                    pk.y = pack_h2((&r[2].x)[k], (&r[3].x)[k]);
                    pk.z = pack_h2((&r[4].x)[k], (&r[5].x)[k]);
                    pk.w = pack_h2((&r[6].x)[k], (&r[7].x)[k]);
                    *(uint4*)(shp + swz_off((i << 2) + k)) = pk;
                }
            }
            __threadfence_block();                 // STS visible before arrive
            BAR_ARRIVE(1 + (t & 1));               // signal buffer full
        }
    } else {
        // ---------------- consumer: 512 threads ----------------
        const int npair = out_dim >> 1;
        for (int t = 0; t < G; t++) {
            const int g  = (int)blockIdx.x + t * (int)gridDim.x;
            const int rb = g * ROWS;
            const __half* shp = sh + (t & 1) * tile_halfs;
            BAR_SYNC(1 + (t & 1));                 // wait buffer full

            for (int q = tid; q < npair; q += NCONS) {
                const uint4 rE = g_tabE[q];
                const uint4 rO = g_tabO[q];

                const uint4 aE = *(const uint4*)(shp + (rE.z & 0xFFFFu));
                const uint4 bE = *(const uint4*)(shp + (rE.z >> 16));
                const uint4 aO = *(const uint4*)(shp + (rO.z & 0xFFFFu));
                const uint4 bO = *(const uint4*)(shp + (rO.z >> 16));

                const float2 cE01 = h22f2(rE.x);
                const float2 cE23 = h22f2(rE.y);
                const float2 cO01 = h22f2(rO.x);
                const float2 cO23 = h22f2(rO.y);

                float* op = out + (size_t)rb * out_dim + 2 * q;
#pragma unroll
                for (int r2 = 0; r2 < 4; r2++) {
                    const float2 vaE = h22f2((&aE.x)[r2]);
                    const float2 vbE = h22f2((&bE.x)[r2]);
                    const float2 vaO = h22f2((&aO.x)[r2]);
                    const float2 vbO = h22f2((&bO.x)[r2]);

                    if (FULL || rb + 2 * r2 < batch) {
                        float2 res;
                        res.x = fmaf(vaE.x, fmaf(vbE.x, cE23.y, cE01.y),
                                     fmaf(vbE.x, cE23.x, cE01.x));
                        res.y = fmaf(vaO.x, fmaf(vbO.x, cO23.y, cO01.y),
                                     fmaf(vbO.x, cO23.x, cO01.x));
                        *(float2*)(op + (size_t)(2 * r2) * out_dim) = res;
                    }
                    if (FULL || rb + 2 * r2 + 1 < batch) {
                        float2 res;
                        res.x = fmaf(vaE.y, fmaf(vbE.y, cE23.y, cE01.y),
                                     fmaf(vbE.y, cE23.x, cE01.x));
                        res.y = fmaf(vaO.y, fmaf(vbO.y, cO23.y, cO01.y),
                                     fmaf(vbO.y, cO23.x, cO01.x));
                        *(float2*)(op + (size_t)(2 * r2 + 1) * out_dim) = res;
                    }
                }
            }
            BAR_ARRIVE(3 + (t & 1));               // signal buffer empty
        }
    }
}

extern "C" void kernel_launch(void* const* d_in, const int* in_sizes, int n_in,
                              void* d_out, int out_size) {
    const float* x   = (const float*)d_in[0];
    const void*  idx = d_in[1];
    const float* w   = (const float*)d_in[2];
    float*       out = (float*)d_out;

    const int out_dim = in_sizes[2] / 16;         // weight is (out_dim, 16)
    const int batch   = out_size / out_dim;       // out is (batch, out_dim)
    const int in_dim  = in_sizes[0] / batch;      // x is (batch, in_dim)

    precompute_kernel<<<(out_dim + 255) / 256, 256>>>(idx, w, out_dim);

    const int ngroups = (batch + ROWS - 1) / ROWS;
    int dev = 0, nsm = 148;
    cudaGetDevice(&dev);
    cudaDeviceGetAttribute(&nsm, cudaDevAttrMultiProcessorCount, dev);
    const int grid = (ngroups < nsm) ? ngroups : nsm;

    const size_t smem = 2 * (size_t)in_dim * ROWS * sizeof(__half);  // 128 KiB @ 4096

    if (batch % ROWS == 0) {
        cudaFuncSetAttribute(logic_persist_kernel<true>,
                             cudaFuncAttributeMaxDynamicSharedMemorySize, (int)smem);
        logic_persist_kernel<true><<<grid, THREADS, smem>>>(
            x, out, in_dim, out_dim, batch, ngroups);
    } else {
        cudaFuncSetAttribute(logic_persist_kernel<false>,
                             cudaFuncAttributeMaxDynamicSharedMemorySize, (int)smem);
        logic_persist_kernel<false><<<grid, THREADS, smem>>>(
            x, out, in_dim, out_dim, batch, ngroups);
    }
}

// round 13
// speedup vs baseline: 1.1718x; 1.1718x over previous
#include <cuda_runtime.h>
#include <cuda_fp16.h>

// LogicDense: out[i][j] = c0 + c1*a + c2*b + c3*a*b
//   a = x[i, idx0[j]], b = x[i, idx1[j]]
//
// R13 = R11 (best main: 38.7 us; persistent/warp-spec R12 REGRESSED -> reverted)
//   + two changes driven by the LTS-cap model (x 64 + out 128 + table 64 MiB
//     = 256 MiB over ~6.9 TB/s ~= 37 us ~= measured):
//   1) table slimmed 32 -> 24 B per column pair: one uint4 of 4 x half2 coeffs
//      (cE01,cE23,cO01,cO23) + one uint2 of packed swizzled offsets.
//   2) PDL: main kernel launched with ProgrammaticStreamSerialization; its
//      staging phase (only needs x) overlaps the precompute kernel, and
//      cudaGridDependencySynchronize() gates only the table-reading loop.
//      Attacks the fixed ~8.9 us total-main launch-serialization gap.

#define ROWS 8
#define THREADS 512
#define MAX_OUT 16384

__device__ uint4 g_cf[MAX_OUT / 2];   // per-pair coeffs: h2(c0,c1)E, h2(c2,c3)E, h2(c0,c1)O, h2(c2,c3)O
__device__ uint2 g_of[MAX_OUT / 2];   // per-pair offsets: (offAE|offBE<<16, offAO|offBO<<16)

__constant__ float c_T[64] = {
    0.f, 0.f, 0.f, 0.f,
    0.f, 0.f, 0.f, 1.f,
    0.f, 1.f, 0.f,-1.f,
    0.f, 1.f, 0.f, 0.f,
    0.f, 0.f, 1.f,-1.f,
    0.f, 0.f, 1.f, 0.f,
    0.f, 1.f, 1.f,-2.f,
    0.f, 1.f, 1.f,-1.f,
    1.f,-1.f,-1.f, 1.f,
    1.f,-1.f,-1.f, 2.f,
    1.f, 0.f,-1.f, 0.f,
    1.f, 0.f,-1.f, 1.f,
    1.f,-1.f, 0.f, 0.f,
    1.f,-1.f, 0.f, 1.f,
    1.f, 0.f, 0.f,-1.f,
    1.f, 0.f, 0.f, 0.f
};

__device__ __forceinline__ int swz_off(int idx) {
    // half-index of the 8-row group of element idx in the swizzled tile
    return (idx << 3) ^ (((idx >> 3) & 7) << 3);
}

__device__ __forceinline__ void softmax_coef(const float* __restrict__ w, int col,
                                             unsigned int& c01u, unsigned int& c23u) {
    const float4* w4 = (const float4*)(w + (size_t)col * 16);
    float4 wa = w4[0], wb = w4[1], wc = w4[2], wd = w4[3];
    float wv[16] = {wa.x, wa.y, wa.z, wa.w, wb.x, wb.y, wb.z, wb.w,
                    wc.x, wc.y, wc.z, wc.w, wd.x, wd.y, wd.z, wd.w};
    float m = -1e30f;
#pragma unroll
    for (int k = 0; k < 16; k++) m = fmaxf(m, wv[k]);
    float s = 0.f;
#pragma unroll
    for (int k = 0; k < 16; k++) {
        wv[k] = __expf(wv[k] - m);
        s += wv[k];
    }
    float inv = 1.f / s;
    float c0 = 0.f, c1 = 0.f, c2 = 0.f, c3 = 0.f;
#pragma unroll
    for (int k = 0; k < 16; k++) {
        float p = wv[k] * inv;
        c0 = fmaf(p, c_T[4 * k + 0], c0);
        c1 = fmaf(p, c_T[4 * k + 1], c1);
        c2 = fmaf(p, c_T[4 * k + 2], c2);
        c3 = fmaf(p, c_T[4 * k + 3], c3);
    }
    __half2 c01 = __floats2half2_rn(c0, c1);
    __half2 c23 = __floats2half2_rn(c2, c3);
    c01u = *(unsigned int*)&c01;
    c23u = *(unsigned int*)&c23;
}

__global__ void precompute_kernel(const void* __restrict__ idx_raw,
                                  const float* __restrict__ w,
                                  int out_dim) {
    // dtype detect: odd u32 words of the first 64 words are all zero iff the
    // buffer is int64 (high words of indices < in_dim). Warp-ballot, no smem.
    const unsigned int* u = (const unsigned int*)idx_raw;
    unsigned int probe = u[2 * (threadIdx.x & 31) + 1];
    const int is64 = !__any_sync(0xFFFFFFFFu, probe != 0u);

    const int npair = out_dim >> 1;
    int q = blockIdx.x * blockDim.x + threadIdx.x;   // pair index
    if (q >= npair) return;
    const int jE = 2 * q, jO = 2 * q + 1;

    uint4 cf;
    softmax_coef(w, jE, cf.x, cf.y);
    softmax_coef(w, jO, cf.z, cf.w);
    g_cf[q] = cf;

    int aE, bE, aO, bO;
    if (is64) {
        const long long* p = (const long long*)idx_raw;
        aE = (int)p[jE]; bE = (int)p[out_dim + jE];
        aO = (int)p[jO]; bO = (int)p[out_dim + jO];
    } else {
        const int* p = (const int*)idx_raw;
        aE = p[jE]; bE = p[out_dim + jE];
        aO = p[jO]; bO = p[out_dim + jO];
    }
    uint2 of;
    of.x = (unsigned int)swz_off(aE) | ((unsigned int)swz_off(bE) << 16);
    of.y = (unsigned int)swz_off(aO) | ((unsigned int)swz_off(bO) << 16);
    g_of[q] = of;
}

__device__ __forceinline__ unsigned int pack_h2(float lo, float hi) {
    __half2 h = __floats2half2_rn(lo, hi);
    return *(unsigned int*)&h;
}

__device__ __forceinline__ float2 h22f2(unsigned int u) {
    return __half22float2(*(const __half2*)&u);
}

template <bool FULL>
__global__ __launch_bounds__(THREADS) void logic_main_kernel(
    const float* __restrict__ x,
    float* __restrict__ out,
    int in_dim, int out_dim, int batch) {
    extern __shared__ __half sh[];   // in_dim * 8 halfs (64 KiB @ 4096), swizzled

    const int rb = blockIdx.x * ROWS;
    const int nr = FULL ? ROWS : min(ROWS, batch - rb);

    // ---- stage 8 rows (independent of the table -> overlaps precompute) ----
    {
        const int n4 = in_dim >> 2;   // element-chunks of 4
        const float* xb = x + (size_t)rb * in_dim;
        for (int i = threadIdx.x; i < n4; i += blockDim.x) {
            float4 r[ROWS];
#pragma unroll
            for (int rr = 0; rr < ROWS; rr++) {
                int row = (FULL || rr < nr) ? rr : 0;
                r[rr] = *(const float4*)(xb + (size_t)row * in_dim + (i << 2));
            }
#pragma unroll
            for (int k = 0; k < 4; k++) {
                uint4 pk;
                pk.x = pack_h2((&r[0].x)[k], (&r[1].x)[k]);
                pk.y = pack_h2((&r[2].x)[k], (&r[3].x)[k]);
                pk.z = pack_h2((&r[4].x)[k], (&r[5].x)[k]);
                pk.w = pack_h2((&r[6].x)[k], (&r[7].x)[k]);
                const int idx = (i << 2) + k;
                *(uint4*)(sh + swz_off(idx)) = pk;
            }
        }
    }
    __syncthreads();

    // PDL: precompute's table writes must be visible before the compute loop.
    cudaGridDependencySynchronize();

    // ---- compute: column pair per thread, records prefetched 1 iter ahead ----
    const int npair = out_dim >> 1;
    int q = threadIdx.x;
    if (q < npair) {
        uint4 cf = g_cf[q];
        uint2 of = g_of[q];
        while (true) {
            const int qn = q + (int)blockDim.x;
            uint4 cfn; uint2 ofn;
            const bool more = (qn < npair);
            if (more) {             // prefetch next records before computing
                cfn = g_cf[qn];
                ofn = g_of[qn];
            }

            const uint4 aE = *(const uint4*)(sh + (of.x & 0xFFFFu));
            const uint4 bE = *(const uint4*)(sh + (of.x >> 16));
            const uint4 aO = *(const uint4*)(sh + (of.y & 0xFFFFu));
            const uint4 bO = *(const uint4*)(sh + (of.y >> 16));

            const float2 cE01 = h22f2(cf.x);
            const float2 cE23 = h22f2(cf.y);
            const float2 cO01 = h22f2(cf.z);
            const float2 cO23 = h22f2(cf.w);

            float* op = out + (size_t)rb * out_dim + 2 * q;
#pragma unroll
            for (int r2 = 0; r2 < 4; r2++) {
                const float2 vaE = h22f2((&aE.x)[r2]);
                const float2 vbE = h22f2((&bE.x)[r2]);
                const float2 vaO = h22f2((&aO.x)[r2]);
                const float2 vbO = h22f2((&bO.x)[r2]);

                // row 2*r2
                if (FULL || 2 * r2 < nr) {
                    float2 res;
                    res.x = fmaf(vaE.x, fmaf(vbE.x, cE23.y, cE01.y),
                                 fmaf(vbE.x, cE23.x, cE01.x));
                    res.y = fmaf(vaO.x, fmaf(vbO.x, cO23.y, cO01.y),
                                 fmaf(vbO.x, cO23.x, cO01.x));
                    *(float2*)(op + (size_t)(2 * r2) * out_dim) = res;
                }
                // row 2*r2+1
                if (FULL || 2 * r2 + 1 < nr) {
                    float2 res;
                    res.x = fmaf(vaE.y, fmaf(vbE.y, cE23.y, cE01.y),
                                 fmaf(vbE.y, cE23.x, cE01.x));
                    res.y = fmaf(vaO.y, fmaf(vbO.y, cO23.y, cO01.y),
                                 fmaf(vbO.y, cO23.x, cO01.x));
                    *(float2*)(op + (size_t)(2 * r2 + 1) * out_dim) = res;
                }
            }

            if (!more) break;
            q = qn;
            cf = cfn;
            of = ofn;
        }
    }
}

template <bool FULL>
static void launch_main_pdl(const float* x, float* out,
                            int in_dim, int out_dim, int batch,
                            int grid, size_t smem) {
    cudaFuncSetAttribute(logic_main_kernel<FULL>,
                         cudaFuncAttributeMaxDynamicSharedMemorySize, (int)smem);
    cudaLaunchConfig_t cfg = {};
    cfg.gridDim = dim3((unsigned)grid, 1, 1);
    cfg.blockDim = dim3(THREADS, 1, 1);
    cfg.dynamicSmemBytes = smem;
    cudaLaunchAttribute attr[1];
    attr[0].id = cudaLaunchAttributeProgrammaticStreamSerialization;
    attr[0].val.programmaticStreamSerializationAllowed = 1;
    cfg.attrs = attr;
    cfg.numAttrs = 1;
    cudaLaunchKernelEx(&cfg, logic_main_kernel<FULL>,
                       x, out, in_dim, out_dim, batch);
}

extern "C" void kernel_launch(void* const* d_in, const int* in_sizes, int n_in,
                              void* d_out, int out_size) {
    const float* x   = (const float*)d_in[0];
    const void*  idx = d_in[1];
    const float* w   = (const float*)d_in[2];
    float*       out = (float*)d_out;

    const int out_dim = in_sizes[2] / 16;         // weight is (out_dim, 16)
    const int batch   = out_size / out_dim;       // out is (batch, out_dim)
    const int in_dim  = in_sizes[0] / batch;      // x is (batch, in_dim)

    const int npair = out_dim >> 1;
    precompute_kernel<<<(npair + 255) / 256, 256>>>(idx, w, out_dim);

    const size_t smem = (size_t)in_dim * ROWS * sizeof(__half);   // 64 KiB @ 4096
    const int grid = (batch + ROWS - 1) / ROWS;

    if (batch % ROWS == 0)
        launch_main_pdl<true>(x, out, in_dim, out_dim, batch, grid, smem);
    else
        launch_main_pdl<false>(x, out, in_dim, out_dim, batch, grid, smem);
}